// round 14
// baseline (speedup 1.0000x reference)
#include <cuda_runtime.h>
#include <cuda_bf16.h>
#include <cstdint>

// ===================== Problem constants =====================
#define MDIM 4096
#define KDIM 4096
#define NDIM 11008
#define NGROUPS 32

// ===================== GEMM tiling =====================
// CTA 128x128, 4 warps (128 thr) as 2m x 2n, warp tile 64x64.
// 3 stages x 32 KB = 96 KB -> 2 CTAs/SM; regs ~185/thr x 256 thr < 64k.
#define BM 128
#define BN 128
#define BK 64
#define STAGES 3
#define NCHUNK (KDIM / BK)     // 64
#define THREADS 128

#define A_U4 (BM * BK / 8)         // 1024 (16 KB)
#define B_U4 (BN * BK / 8)         // 1024 (16 KB)
#define STAGE_U4 (A_U4 + B_U4)     // 2048 (32 KB)
#define SMEM_BYTES (STAGES * STAGE_U4 * 16)   // 98304 (96 KB)

// Scratch: x as bf16, dequantized W as bf16
__device__ __nv_bfloat16 g_Xb[(size_t)MDIM * KDIM];
__device__ __nv_bfloat16 g_Wd[(size_t)NDIM * KDIM];

// ===================== PTX helpers =====================
#define CP_ASYNC_CG(dst_u32, src_ptr) \
    asm volatile("cp.async.cg.shared.global [%0], [%1], 16;" \
                 :: "r"(dst_u32), "l"(src_ptr) : "memory")
#define CP_COMMIT() asm volatile("cp.async.commit_group;" ::: "memory")
#define CP_WAIT(n) asm volatile("cp.async.wait_group %0;" :: "n"(n) : "memory")
#define LDSM_X4(R0, R1, R2, R3, ADDR) \
    asm volatile("ldmatrix.sync.aligned.m8n8.x4.shared.b16 {%0,%1,%2,%3}, [%4];" \
                 : "=r"(R0), "=r"(R1), "=r"(R2), "=r"(R3) : "r"(ADDR))
#define MMA_BF16(D, A0, A1, A2, A3, B0, B1) \
    asm volatile("mma.sync.aligned.m16n8k16.row.col.f32.bf16.bf16.f32 " \
                 "{%0,%1,%2,%3}, {%4,%5,%6,%7}, {%8,%9}, {%0,%1,%2,%3};" \
                 : "+f"((D)[0]), "+f"((D)[1]), "+f"((D)[2]), "+f"((D)[3]) \
                 : "r"(A0), "r"(A1), "r"(A2), "r"(A3), "r"(B0), "r"(B1))

static __device__ __forceinline__ uint32_t smem_u32(const void* p) {
    return (uint32_t)__cvta_generic_to_shared(p);
}
static __device__ __forceinline__ float bf16rt(float v) {
    return __bfloat162float(__float2bfloat16_rn(v));
}

// ===================== Kernel 0: merged prepass ==============================
__global__ void __launch_bounds__(256) prepass_kernel(
    const float* __restrict__ X,  __nv_bfloat16* __restrict__ Xb,
    const int*   __restrict__ Wq,
    const float* __restrict__ scales,
    const float* __restrict__ zeros,
    __nv_bfloat16* __restrict__ Wd)
{
    if (blockIdx.x < 8192) {
        uint32_t i = ((uint32_t)blockIdx.x * 256u + threadIdx.x) * 8u;
        float4 v0 = __ldg((const float4*)(X + i));
        float4 v1 = __ldg((const float4*)(X + i + 4));
        ushort4 p;
        unsigned short* pk = (unsigned short*)&p;
        const float* vv0 = (const float*)&v0;
        const float* vv1 = (const float*)&v1;
        #pragma unroll
        for (int j = 0; j < 4; j++) {
            __nv_bfloat16 a = __float2bfloat16_rn(vv0[j]);
            pk[j] = *(unsigned short*)&a;
        }
        *(ushort4*)(Xb + i) = p;
        #pragma unroll
        for (int j = 0; j < 4; j++) {
            __nv_bfloat16 a = __float2bfloat16_rn(vv1[j]);
            pk[j] = *(unsigned short*)&a;
        }
        *(ushort4*)(Xb + i + 4) = p;
    } else {
        uint32_t idx = (((uint32_t)blockIdx.x - 8192u) * 256u + threadIdx.x) * 4u;
        int4 q = *reinterpret_cast<const int4*>(Wq + idx);
        uint32_t n = idx >> 12;
        uint32_t g = (idx & (KDIM - 1)) >> 7;
        float s = __ldg(scales + n * NGROUPS + g);
        float z = __ldg(zeros  + n * NGROUPS + g);
        __nv_bfloat162 w01 = __floats2bfloat162_rn(((float)q.x - z) * s, ((float)q.y - z) * s);
        __nv_bfloat162 w23 = __floats2bfloat162_rn(((float)q.z - z) * s, ((float)q.w - z) * s);
        uint2 v;
        v.x = *reinterpret_cast<uint32_t*>(&w01);
        v.y = *reinterpret_cast<uint32_t*>(&w23);
        *reinterpret_cast<uint2*>(Wd + idx) = v;
    }
}

// ===================== Kernel 1: 128x128 GEMM, 64x64 warp tiles, 2 CTA/SM ====
__global__ void __launch_bounds__(THREADS, 2)
gemm_kernel(const __nv_bfloat16* __restrict__ A,
            const __nv_bfloat16* __restrict__ B,
            const float* __restrict__ bias,
            float* __restrict__ out)
{
    extern __shared__ uint4 smem[];

    const int tid  = threadIdx.x;
    const int lane = tid & 31;
    const int wid  = tid >> 5;   // 0..3
    const int wm   = wid & 1;    // 2 m-warps x 64 rows
    const int wn   = wid >> 1;   // 2 n-warps x 64 cols
    const int m0   = blockIdx.y * BM;
    const int n0   = blockIdx.x * BN;

    const uint32_t sbase = smem_u32(smem);

    // ---- loaders: 128 threads x 16B; A: 8 row-strides of 16, B: 8 ----
    const int g  = tid & 7;
    const int r0 = tid >> 3;                  // 0..15
    const int gsw = g ^ (r0 & 7);             // rows stride 16 -> invariant
    const __nv_bfloat16* asrc = A + (size_t)(m0 + r0) * KDIM + g * 8;
    const __nv_bfloat16* bsrc = B + (size_t)(n0 + r0) * KDIM + g * 8;

    #define ISSUE_STAGE(s, kc) do {                                            \
        uint32_t _sa = sbase + (uint32_t)(s) * (STAGE_U4 * 16);                 \
        uint32_t _sb = _sa + A_U4 * 16;                                         \
        int _ko = (kc) * BK;                                                    \
        _Pragma("unroll")                                                       \
        for (int _i = 0; _i < 8; _i++) {                                        \
            int _row = r0 + _i * 16;                                            \
            CP_ASYNC_CG(_sa + (uint32_t)(_row * 8 + gsw) * 16,                  \
                        asrc + (size_t)_i * 16 * KDIM + _ko);                   \
            CP_ASYNC_CG(_sb + (uint32_t)(_row * 8 + gsw) * 16,                  \
                        bsrc + (size_t)_i * 16 * KDIM + _ko);                   \
        }                                                                       \
    } while (0)

    #pragma unroll
    for (int s = 0; s < STAGES - 1; s++) {
        ISSUE_STAGE(s, s);
        CP_COMMIT();
    }

    // 64x64 warp tile: 4 m16 x 8 n8 = 128 f32 accumulators
    float acc[4][8][4];
    #pragma unroll
    for (int i = 0; i < 4; i++)
        #pragma unroll
        for (int j = 0; j < 8; j++)
            #pragma unroll
            for (int c = 0; c < 4; c++) acc[i][j][c] = 0.0f;

    const int lrow = lane & 15;
    const int lkg  = lane >> 4;

    int s = 0;
    int sl = STAGES - 1;
    for (int kc = 0; kc < NCHUNK; kc++) {
        CP_WAIT(STAGES - 2);
        __syncthreads();

        const uint32_t sa = sbase + (uint32_t)s * (STAGE_U4 * 16);
        const uint32_t sb = sa + A_U4 * 16;

        #pragma unroll
        for (int ks = 0; ks < BK / 16; ks++) {
            // A fragments: 4 m16 tiles (64 rows)
            uint32_t af[4][4];
            #pragma unroll
            for (int i = 0; i < 4; i++) {
                int row = wm * 64 + i * 16 + lrow;
                int kg  = ks * 2 + lkg;
                uint32_t addr = sa + (uint32_t)(row * 8 + (kg ^ (row & 7))) * 16;
                LDSM_X4(af[i][0], af[i][1], af[i][2], af[i][3], addr);
            }
            // B fragments: 4 n16 tiles -> 8 n8 tiles (64 cols)
            uint32_t bf[8][2];
            #pragma unroll
            for (int j = 0; j < 4; j++) {
                int row = wn * 64 + j * 16 + lrow;
                int kg  = ks * 2 + lkg;
                uint32_t addr = sb + (uint32_t)(row * 8 + (kg ^ (row & 7))) * 16;
                uint32_t t0, t1, t2, t3;
                LDSM_X4(t0, t1, t2, t3, addr);
                bf[2 * j][0] = t0; bf[2 * j][1] = t2;
                bf[2 * j + 1][0] = t1; bf[2 * j + 1][1] = t3;
            }
            // 32 MMAs
            #pragma unroll
            for (int i = 0; i < 4; i++)
                #pragma unroll
                for (int j = 0; j < 8; j++)
                    MMA_BF16(acc[i][j], af[i][0], af[i][1], af[i][2], af[i][3],
                             bf[j][0], bf[j][1]);
        }

        if (kc + STAGES - 1 < NCHUNK) {
            ISSUE_STAGE(sl, kc + STAGES - 1);
        }
        CP_COMMIT();
        s  = (s  + 1 == STAGES) ? 0 : s  + 1;
        sl = (sl + 1 == STAGES) ? 0 : sl + 1;
    }

    // ---- epilogue: ref-exact rounding chain, f32 stores ----
    const int qrow = lane >> 2;
    const int qcol = (lane & 3) * 2;
    #pragma unroll
    for (int i = 0; i < 4; i++) {
        int grow = m0 + wm * 64 + i * 16 + qrow;
        #pragma unroll
        for (int j = 0; j < 8; j++) {
            int gcol = n0 + wn * 64 + j * 8 + qcol;
            float b0 = __ldg(bias + gcol);
            float b1 = __ldg(bias + gcol + 1);
            float2 o0, o1;
            o0.x = bf16rt(bf16rt(acc[i][j][0]) + b0);
            o0.y = bf16rt(bf16rt(acc[i][j][1]) + b1);
            o1.x = bf16rt(bf16rt(acc[i][j][2]) + b0);
            o1.y = bf16rt(bf16rt(acc[i][j][3]) + b1);
            *reinterpret_cast<float2*>(out + (size_t)grow * NDIM + gcol) = o0;
            *reinterpret_cast<float2*>(out + (size_t)(grow + 8) * NDIM + gcol) = o1;
        }
    }
    #undef ISSUE_STAGE
}

// ===================== Host launch =====================
extern "C" void kernel_launch(void* const* d_in, const int* in_sizes, int n_in,
                              void* d_out, int out_size)
{
    (void)in_sizes; (void)n_in; (void)out_size;
    const float* x      = (const float*)d_in[0];
    const int*   Wq     = (const int*)d_in[1];
    const float* scales = (const float*)d_in[2];
    const float* zeros  = (const float*)d_in[3];
    const float* bias   = (const float*)d_in[4];
    float*       out    = (float*)d_out;

    void* xb_ptr = nullptr; cudaGetSymbolAddress(&xb_ptr, g_Xb);
    void* wd_ptr = nullptr; cudaGetSymbolAddress(&wd_ptr, g_Wd);

    prepass_kernel<<<52224, 256>>>(x, (__nv_bfloat16*)xb_ptr,
                                   Wq, scales, zeros, (__nv_bfloat16*)wd_ptr);

    cudaFuncSetAttribute(gemm_kernel, cudaFuncAttributeMaxDynamicSharedMemorySize,
                         SMEM_BYTES);
    dim3 grid(NDIM / BN, MDIM / BM);   // (86, 32)
    gemm_kernel<<<grid, THREADS, SMEM_BYTES>>>(
        (const __nv_bfloat16*)xb_ptr, (const __nv_bfloat16*)wd_ptr, bias, out);
}

// round 15
// speedup vs baseline: 1.0564x; 1.0564x over previous
#include <cuda_runtime.h>
#include <cuda_bf16.h>
#include <cstdint>

// ===================== Problem constants =====================
#define MDIM 4096
#define KDIM 4096
#define NDIM 11008
#define NGROUPS 32

// ===================== GEMM tiling =====================
// CTA 128x128, 8 warps (4m x 2n) of 32x64; 3 stages x 32 KB = 96 KB
// -> 2 CTAs/SM. Warp-skewed k-order to break the post-barrier convoy.
#define BM 128
#define BN 128
#define BK 64
#define STAGES 3
#define NCHUNK (KDIM / BK)     // 64
#define THREADS 256
#define NTILE_M (MDIM / BM)    // 32
#define NTILE_N (NDIM / BN)    // 86
#define GROUP_M 8

#define A_U4 (BM * BK / 8)         // 1024 (16 KB)
#define B_U4 (BN * BK / 8)         // 1024 (16 KB)
#define STAGE_U4 (A_U4 + B_U4)     // 2048 (32 KB)
#define SMEM_BYTES (STAGES * STAGE_U4 * 16)   // 98304 (96 KB)

__device__ __nv_bfloat16 g_Xb[(size_t)MDIM * KDIM];
__device__ __nv_bfloat16 g_Wd[(size_t)NDIM * KDIM];

// ===================== PTX helpers =====================
#define CP_ASYNC_CG(dst_u32, src_ptr) \
    asm volatile("cp.async.cg.shared.global [%0], [%1], 16;" \
                 :: "r"(dst_u32), "l"(src_ptr) : "memory")
#define CP_COMMIT() asm volatile("cp.async.commit_group;" ::: "memory")
#define CP_WAIT(n) asm volatile("cp.async.wait_group %0;" :: "n"(n) : "memory")
#define LDSM_X4(R0, R1, R2, R3, ADDR) \
    asm volatile("ldmatrix.sync.aligned.m8n8.x4.shared.b16 {%0,%1,%2,%3}, [%4];" \
                 : "=r"(R0), "=r"(R1), "=r"(R2), "=r"(R3) : "r"(ADDR))
#define MMA_BF16(D, A0, A1, A2, A3, B0, B1) \
    asm volatile("mma.sync.aligned.m16n8k16.row.col.f32.bf16.bf16.f32 " \
                 "{%0,%1,%2,%3}, {%4,%5,%6,%7}, {%8,%9}, {%0,%1,%2,%3};" \
                 : "+f"((D)[0]), "+f"((D)[1]), "+f"((D)[2]), "+f"((D)[3]) \
                 : "r"(A0), "r"(A1), "r"(A2), "r"(A3), "r"(B0), "r"(B1))

static __device__ __forceinline__ uint32_t smem_u32(const void* p) {
    return (uint32_t)__cvta_generic_to_shared(p);
}
static __device__ __forceinline__ float bf16rt(float v) {
    return __bfloat162float(__float2bfloat16_rn(v));
}

// ===================== Kernel 0: merged prepass ==============================
__global__ void __launch_bounds__(256) prepass_kernel(
    const float* __restrict__ X,  __nv_bfloat16* __restrict__ Xb,
    const int*   __restrict__ Wq,
    const float* __restrict__ scales,
    const float* __restrict__ zeros,
    __nv_bfloat16* __restrict__ Wd)
{
    if (blockIdx.x < 8192) {
        uint32_t i = ((uint32_t)blockIdx.x * 256u + threadIdx.x) * 8u;
        float4 v0 = __ldg((const float4*)(X + i));
        float4 v1 = __ldg((const float4*)(X + i + 4));
        ushort4 p;
        unsigned short* pk = (unsigned short*)&p;
        const float* vv0 = (const float*)&v0;
        const float* vv1 = (const float*)&v1;
        #pragma unroll
        for (int j = 0; j < 4; j++) {
            __nv_bfloat16 a = __float2bfloat16_rn(vv0[j]);
            pk[j] = *(unsigned short*)&a;
        }
        *(ushort4*)(Xb + i) = p;
        #pragma unroll
        for (int j = 0; j < 4; j++) {
            __nv_bfloat16 a = __float2bfloat16_rn(vv1[j]);
            pk[j] = *(unsigned short*)&a;
        }
        *(ushort4*)(Xb + i + 4) = p;
    } else {
        uint32_t idx = (((uint32_t)blockIdx.x - 8192u) * 256u + threadIdx.x) * 4u;
        int4 q = *reinterpret_cast<const int4*>(Wq + idx);
        uint32_t n = idx >> 12;
        uint32_t g = (idx & (KDIM - 1)) >> 7;
        float s = __ldg(scales + n * NGROUPS + g);
        float z = __ldg(zeros  + n * NGROUPS + g);
        __nv_bfloat162 w01 = __floats2bfloat162_rn(((float)q.x - z) * s, ((float)q.y - z) * s);
        __nv_bfloat162 w23 = __floats2bfloat162_rn(((float)q.z - z) * s, ((float)q.w - z) * s);
        uint2 v;
        v.x = *reinterpret_cast<uint32_t*>(&w01);
        v.y = *reinterpret_cast<uint32_t*>(&w23);
        *reinterpret_cast<uint2*>(Wd + idx) = v;
    }
}

// ===================== Kernel 1: 128x128 GEMM, warp-skewed k ==================
__global__ void __launch_bounds__(THREADS, 2)
gemm_kernel(const __nv_bfloat16* __restrict__ A,
            const __nv_bfloat16* __restrict__ B,
            const float* __restrict__ bias,
            float* __restrict__ out)
{
    extern __shared__ uint4 smem[];

    const int tid  = threadIdx.x;
    const int lane = tid & 31;
    const int wid  = tid >> 5;
    const int wm   = wid & 3;    // 4 m-warps x 32 rows
    const int wn   = wid >> 2;   // 2 n-warps x 64 cols

    // ---- grid rasterization: GROUP_M m-tiles per n strip ----
    const int pid   = blockIdx.x;
    const int group = pid / (GROUP_M * NTILE_N);
    const int rem   = pid % (GROUP_M * NTILE_N);
    const int pid_m = group * GROUP_M + (rem % GROUP_M);
    const int pid_n = rem / GROUP_M;
    const int m0    = pid_m * BM;
    const int n0    = pid_n * BN;

    const uint32_t sbase = smem_u32(smem);

    const int g  = tid & 7;
    const int r0 = tid >> 3;
    const int gsw = g ^ (r0 & 7);
    const __nv_bfloat16* asrc = A + (size_t)(m0 + r0) * KDIM + g * 8;
    const __nv_bfloat16* bsrc = B + (size_t)(n0 + r0) * KDIM + g * 8;

    #define ISSUE_STAGE(s, kc) do {                                            \
        uint32_t _sa = sbase + (uint32_t)(s) * (STAGE_U4 * 16);                 \
        uint32_t _sb = _sa + A_U4 * 16;                                         \
        int _ko = (kc) * BK;                                                    \
        _Pragma("unroll")                                                       \
        for (int _i = 0; _i < 4; _i++) {                                        \
            int _row = r0 + _i * 32;                                            \
            CP_ASYNC_CG(_sa + (uint32_t)(_row * 8 + gsw) * 16,                  \
                        asrc + (size_t)_i * 32 * KDIM + _ko);                   \
            CP_ASYNC_CG(_sb + (uint32_t)(_row * 8 + gsw) * 16,                  \
                        bsrc + (size_t)_i * 32 * KDIM + _ko);                   \
        }                                                                       \
    } while (0)

    #pragma unroll
    for (int s = 0; s < STAGES - 1; s++) {
        ISSUE_STAGE(s, s);
        CP_COMMIT();
    }

    float acc[2][8][4];
    #pragma unroll
    for (int i = 0; i < 2; i++)
        #pragma unroll
        for (int j = 0; j < 8; j++)
            #pragma unroll
            for (int c = 0; c < 4; c++) acc[i][j][c] = 0.0f;

    const int lrow = lane & 15;
    const int lkg  = lane >> 4;
    const int kskew = wid & 3;        // per-warp k-phase offset

    int s = 0;
    int sl = STAGES - 1;
    for (int kc = 0; kc < NCHUNK; kc++) {
        CP_WAIT(STAGES - 2);
        __syncthreads();

        const uint32_t sa = sbase + (uint32_t)s * (STAGE_U4 * 16);
        const uint32_t sb = sa + A_U4 * 16;

        #pragma unroll
        for (int kk = 0; kk < BK / 16; kk++) {
            const int ks = (kk + kskew) & 3;   // warp-skewed k16 step

            // A fragments: 2 m16 tiles
            uint32_t af[2][4];
            #pragma unroll
            for (int i = 0; i < 2; i++) {
                int row = wm * 32 + i * 16 + lrow;
                int kg  = ks * 2 + lkg;
                uint32_t addr = sa + (uint32_t)(row * 8 + (kg ^ (row & 7))) * 16;
                LDSM_X4(af[i][0], af[i][1], af[i][2], af[i][3], addr);
            }
            // B fragments interleaved with their MMAs
            #pragma unroll
            for (int j = 0; j < 4; j++) {
                int row = wn * 64 + j * 16 + lrow;
                int kg  = ks * 2 + lkg;
                uint32_t addr = sb + (uint32_t)(row * 8 + (kg ^ (row & 7))) * 16;
                uint32_t t0, t1, t2, t3;
                LDSM_X4(t0, t1, t2, t3, addr);
                #pragma unroll
                for (int i = 0; i < 2; i++) {
                    MMA_BF16(acc[i][2 * j],     af[i][0], af[i][1], af[i][2], af[i][3], t0, t2);
                    MMA_BF16(acc[i][2 * j + 1], af[i][0], af[i][1], af[i][2], af[i][3], t1, t3);
                }
            }
        }

        if (kc + STAGES - 1 < NCHUNK) {
            ISSUE_STAGE(sl, kc + STAGES - 1);
        }
        CP_COMMIT();
        s  = (s  + 1 == STAGES) ? 0 : s  + 1;
        sl = (sl + 1 == STAGES) ? 0 : sl + 1;
    }

    // ---- epilogue: ref-exact rounding chain, f32 stores ----
    const int qrow = lane >> 2;
    const int qcol = (lane & 3) * 2;
    #pragma unroll
    for (int i = 0; i < 2; i++) {
        int grow = m0 + wm * 32 + i * 16 + qrow;
        #pragma unroll
        for (int j = 0; j < 8; j++) {
            int gcol = n0 + wn * 64 + j * 8 + qcol;
            float b0 = __ldg(bias + gcol);
            float b1 = __ldg(bias + gcol + 1);
            float2 o0, o1;
            o0.x = bf16rt(bf16rt(acc[i][j][0]) + b0);
            o0.y = bf16rt(bf16rt(acc[i][j][1]) + b1);
            o1.x = bf16rt(bf16rt(acc[i][j][2]) + b0);
            o1.y = bf16rt(bf16rt(acc[i][j][3]) + b1);
            *reinterpret_cast<float2*>(out + (size_t)grow * NDIM + gcol) = o0;
            *reinterpret_cast<float2*>(out + (size_t)(grow + 8) * NDIM + gcol) = o1;
        }
    }
    #undef ISSUE_STAGE
}

// ===================== Host launch =====================
extern "C" void kernel_launch(void* const* d_in, const int* in_sizes, int n_in,
                              void* d_out, int out_size)
{
    (void)in_sizes; (void)n_in; (void)out_size;
    const float* x      = (const float*)d_in[0];
    const int*   Wq     = (const int*)d_in[1];
    const float* scales = (const float*)d_in[2];
    const float* zeros  = (const float*)d_in[3];
    const float* bias   = (const float*)d_in[4];
    float*       out    = (float*)d_out;

    void* xb_ptr = nullptr; cudaGetSymbolAddress(&xb_ptr, g_Xb);
    void* wd_ptr = nullptr; cudaGetSymbolAddress(&wd_ptr, g_Wd);

    prepass_kernel<<<52224, 256>>>(x, (__nv_bfloat16*)xb_ptr,
                                   Wq, scales, zeros, (__nv_bfloat16*)wd_ptr);

    cudaFuncSetAttribute(gemm_kernel, cudaFuncAttributeMaxDynamicSharedMemorySize,
                         SMEM_BYTES);
    gemm_kernel<<<NTILE_M * NTILE_N, THREADS, SMEM_BYTES>>>(
        (const __nv_bfloat16*)xb_ptr, (const __nv_bfloat16*)wd_ptr, bias, out);
}